// round 16
// baseline (speedup 1.0000x reference)
#include <cuda_runtime.h>
#include <cuda_fp16.h>
#include <cstdint>

#define NN 10000
#define EE 320000
#define DD 256

// ---------------- scratch (static device globals; no allocation) ----------------
__device__ float g_esrc[NN * DD];
__device__ float g_edst[NN * DD];
__device__ float g_fsrc[NN * DD];
__device__ float g_agg[NN * DD];
__device__ float g_outdeg[NN];
__device__ float g_indeg[NN];
// weights^T as single fp16, pre-swizzled per K32 chunk, paired-row layout.
// matrix m: 0=w_edge, 1=w_src, 2=w_dst, 3=weight ; base = m*8192 (uint4 units)
// within: c*1024 + (n>>1)*8 + (n&1)*4 + (u ^ ((n>>1)&3))
__device__ uint4 g_Bsw[4 * 8192];

// ---------------- helpers ----------------
__device__ __forceinline__ uint32_t smem_to_u32(const void* p) {
    uint32_t a;
    asm("{ .reg .u64 t; cvta.to.shared.u64 t, %1; cvt.u32.u64 %0, t; }" : "=r"(a) : "l"(p));
    return a;
}
__device__ __forceinline__ void ldm_x4(uint32_t& r0, uint32_t& r1, uint32_t& r2, uint32_t& r3,
                                       uint32_t addr) {
    asm volatile("ldmatrix.sync.aligned.m8n8.x4.shared.b16 {%0,%1,%2,%3}, [%4];"
                 : "=r"(r0), "=r"(r1), "=r"(r2), "=r"(r3) : "r"(addr));
}
__device__ __forceinline__ void mma16816(float* c, const uint32_t* a, const uint32_t* b) {
    asm volatile(
        "mma.sync.aligned.m16n8k16.row.col.f32.f16.f16.f32 "
        "{%0,%1,%2,%3}, {%4,%5,%6,%7}, {%8,%9}, {%0,%1,%2,%3};"
        : "+f"(c[0]), "+f"(c[1]), "+f"(c[2]), "+f"(c[3])
        : "r"(a[0]), "r"(a[1]), "r"(a[2]), "r"(a[3]), "r"(b[0]), "r"(b[1]));
}
#define CP_ASYNC16(saddr, gptr) \
    asm volatile("cp.async.cg.shared.global [%0], [%1], 16;" :: "r"(saddr), "l"(gptr) : "memory")
#define CP_COMMIT() asm volatile("cp.async.commit_group;" ::: "memory")
#define CP_WAIT_ALL() asm volatile("cp.async.wait_group 0;" ::: "memory")

// pack two fp32 into fp16x2 hi + residual fp16x2 lo (low 16 bits = first elem)
__device__ __forceinline__ uint32_t split_pair_f16(float a, float b, uint32_t& lo) {
    __half ha = __float2half(a), hb = __float2half(b);
    __half la = __float2half(a - __half2float(ha));
    __half lb = __float2half(b - __half2float(hb));
    lo = ((uint32_t)__half_as_ushort(lb) << 16) | (uint32_t)__half_as_ushort(la);
    return ((uint32_t)__half_as_ushort(hb) << 16) | (uint32_t)__half_as_ushort(ha);
}
__device__ __forceinline__ uint32_t pack_f16(float a, float b) {
    __half ha = __float2half(a), hb = __float2half(b);
    return ((uint32_t)__half_as_ushort(hb) << 16) | (uint32_t)__half_as_ushort(ha);
}

// ---------------- launch 0: weight prep (4 matrices, single fp16) + zero ----------------
__global__ void fuse0_kernel(const float* __restrict__ w_edge,
                             const float* __restrict__ w_src,
                             const float* __restrict__ w_dst,
                             const float* __restrict__ weight) {
    int t = blockIdx.x * blockDim.x + threadIdx.x;
    if (t < NN * DD) g_agg[t] = 0.f;
    if (t < NN) { g_outdeg[t] = 0.f; g_indeg[t] = 0.f; }
    if (t < 4 * 8192) {
        int m = t >> 13;                // matrix id
        int w = t & 8191;
        int n = w & 255;
        int g = w >> 8;                 // 0..31
        int c = g >> 2, u = g & 3;      // K32 chunk, k8-unit
        const float* W = (m == 0) ? w_edge : (m == 1) ? w_src : (m == 2) ? w_dst : weight;
        uint32_t p[4];
        #pragma unroll
        for (int j = 0; j < 4; j++) {
            int k = c * 32 + u * 8 + 2 * j;
            p[j] = pack_f16(W[(size_t)k * DD + n], W[(size_t)(k + 1) * DD + n]);
        }
        int di = m * 8192 + c * 1024 + (n >> 1) * 8 + (n & 1) * 4 + (u ^ ((n >> 1) & 3));
        g_Bsw[di] = make_uint4(p[0], p[1], p[2], p[3]);
    }
}

// ---------------- launch 1: degrees ----------------
__global__ void degree_kernel(const int* __restrict__ src, const int* __restrict__ dst) {
    int e = blockIdx.x * blockDim.x + threadIdx.x;
    if (e < EE) {
        atomicAdd(&g_outdeg[src[e]], 1.f);
        atomicAdd(&g_indeg[dst[e]], 1.f);
    }
}

// ---------------- SMEM layout for MMA kernels (per CTA) ----------------
// B ring: 2 slots x 16KB = 32KB ; A: 2 bufs x 8KB (hi 4KB + lo 4KB) = 16KB
static constexpr int S_B   = 0;
static constexpr int S_A   = 32768;
static constexpr int S_IDX = 49152;      // 64 src + 64 dst ints = 512B
static constexpr int S_TOTAL = 49664;    // ~48.5KB ; regs cap at 2 CTAs/SM

// paired-row swizzled offset for a (row, k8-unit) 16B tile
__device__ __forceinline__ uint32_t prow_off(uint32_t r, uint32_t u) {
    return (r >> 1) * 128u + (r & 1) * 64u + ((u ^ ((r >> 1) & 3u)) << 4);
}

// =====================================================================
// Shared mainloop: acc[2][8][4] = A(64 x 256, fp16 hi+lo) @ B16^T
// =====================================================================
struct MmaCtx {
    float acc[2][8][4];
};

__device__ __forceinline__ void run_mainloop(
    MmaCtx& ctx, uint32_t sb, const float* gA, const uint4* gB,
    int tid, int lane, int warp_m, int warp_n, int arow, int au)
{
    #pragma unroll
    for (int mt = 0; mt < 2; mt++)
        #pragma unroll
        for (int nt = 0; nt < 8; nt++)
            #pragma unroll
            for (int i = 0; i < 4; i++) ctx.acc[mt][nt][i] = 0.f;

    // prologue: B chunk 0 into slot 0 (16KB = 1024 units)
    #pragma unroll
    for (int i = 0; i < 4; i++) {
        int idx = tid + i * 256;
        CP_ASYNC16(sb + S_B + idx * 16, gB + idx);
    }
    CP_COMMIT();

    // A(0): load + convert into Abuf0
    float4 rx0 = *(const float4*)(gA);
    float4 rx1 = *(const float4*)(gA + 4);
    {
        uint32_t l0, l1, l2, l3;
        uint32_t h0 = split_pair_f16(rx0.x, rx0.y, l0);
        uint32_t h1 = split_pair_f16(rx0.z, rx0.w, l1);
        uint32_t h2 = split_pair_f16(rx1.x, rx1.y, l2);
        uint32_t h3 = split_pair_f16(rx1.z, rx1.w, l3);
        uint32_t off = prow_off(arow, au);
        asm volatile("st.shared.v4.b32 [%0], {%1,%2,%3,%4};"
                     :: "r"(sb + S_A + off), "r"(h0), "r"(h1), "r"(h2), "r"(h3) : "memory");
        asm volatile("st.shared.v4.b32 [%0], {%1,%2,%3,%4};"
                     :: "r"(sb + S_A + 4096 + off), "r"(l0), "r"(l1), "r"(l2), "r"(l3) : "memory");
    }
    rx0 = *(const float4*)(gA + 32);
    rx1 = *(const float4*)(gA + 36);

    CP_WAIT_ALL();
    __syncthreads();

    const uint32_t a_row = (uint32_t)(lane & 15);
    const uint32_t a_kh  = (uint32_t)(lane >> 4);
    const uint32_t b_nl  = (uint32_t)((lane & 7) + ((lane >> 4) << 3));
    const uint32_t b_kh  = (uint32_t)((lane >> 3) & 1);

    #pragma unroll 1
    for (int s = 0; s < 8; s++) {
        const uint32_t bbase = sb + S_B + (uint32_t)(s & 1) * 16384u;
        const uint32_t abase = sb + S_A + (uint32_t)(s & 1) * 8192u;

        if (s < 7) {
            const uint4* bsrc = gB + (s + 1) * 1024;
            const uint32_t slot = sb + S_B + (uint32_t)((s + 1) & 1) * 16384u;
            #pragma unroll
            for (int i = 0; i < 4; i++) {
                int idx = tid + i * 256;
                CP_ASYNC16(slot + idx * 16, bsrc + idx);
            }
            CP_COMMIT();
        }

        #pragma unroll
        for (int ks = 0; ks < 2; ks++) {
            uint32_t ah[2][4], al[2][4];
            #pragma unroll
            for (int mt = 0; mt < 2; mt++) {
                uint32_t r = (uint32_t)(warp_m * 32 + mt * 16) + a_row;
                uint32_t u = (uint32_t)(ks * 2) + a_kh;
                uint32_t off = prow_off(r, u);
                ldm_x4(ah[mt][0], ah[mt][1], ah[mt][2], ah[mt][3], abase + off);
                ldm_x4(al[mt][0], al[mt][1], al[mt][2], al[mt][3], abase + 4096 + off);
            }
            #pragma unroll
            for (int j = 0; j < 4; j++) {
                uint32_t n = (uint32_t)(warp_n * 64 + j * 16) + b_nl;
                uint32_t u = (uint32_t)(ks * 2) + b_kh;
                uint32_t boff = prow_off(n, u);
                uint32_t bf[4];
                ldm_x4(bf[0], bf[1], bf[2], bf[3], bbase + boff);
                #pragma unroll
                for (int mt = 0; mt < 2; mt++) {
                    mma16816(ctx.acc[mt][2 * j + 0], ah[mt], bf + 0);
                    mma16816(ctx.acc[mt][2 * j + 1], ah[mt], bf + 2);
                    mma16816(ctx.acc[mt][2 * j + 0], al[mt], bf + 0);
                    mma16816(ctx.acc[mt][2 * j + 1], al[mt], bf + 2);
                }
            }
        }

        if (s < 7) {
            uint32_t l0, l1, l2, l3;
            uint32_t h0 = split_pair_f16(rx0.x, rx0.y, l0);
            uint32_t h1 = split_pair_f16(rx0.z, rx0.w, l1);
            uint32_t h2 = split_pair_f16(rx1.x, rx1.y, l2);
            uint32_t h3 = split_pair_f16(rx1.z, rx1.w, l3);
            uint32_t dstb = sb + S_A + (uint32_t)((s + 1) & 1) * 8192u + prow_off(arow, au);
            asm volatile("st.shared.v4.b32 [%0], {%1,%2,%3,%4};"
                         :: "r"(dstb), "r"(h0), "r"(h1), "r"(h2), "r"(h3) : "memory");
            asm volatile("st.shared.v4.b32 [%0], {%1,%2,%3,%4};"
                         :: "r"(dstb + 4096), "r"(l0), "r"(l1), "r"(l2), "r"(l3) : "memory");
            if (s < 6) {
                rx0 = *(const float4*)(gA + (s + 2) * 32);
                rx1 = *(const float4*)(gA + (s + 2) * 32 + 4);
            }
            CP_WAIT_ALL();
            __syncthreads();
        }
    }
}

// assemble this lane's float4 for nt-pair ntp via quad shfl (warp-uniform)
__device__ __forceinline__ float4 quad_f4(const MmaCtx& ctx, int mt, int rh, int ntp, int odd) {
    float v0x = ctx.acc[mt][2 * ntp + 0][rh * 2 + 0];
    float v0y = ctx.acc[mt][2 * ntp + 0][rh * 2 + 1];
    float v1x = ctx.acc[mt][2 * ntp + 1][rh * 2 + 0];
    float v1y = ctx.acc[mt][2 * ntp + 1][rh * 2 + 1];
    float t0 = __shfl_xor_sync(0xffffffffu, v0x, 1);
    float t1 = __shfl_xor_sync(0xffffffffu, v0y, 1);
    float t2 = __shfl_xor_sync(0xffffffffu, v1x, 1);
    float t3 = __shfl_xor_sync(0xffffffffu, v1y, 1);
    float4 dv;
    dv.x = odd ? t2  : v0x;
    dv.y = odd ? t3  : v0y;
    dv.z = odd ? v1x : t0;
    dv.w = odd ? v1y : t1;
    return dv;
}

// ---------------- launch 2: node GEMMs (esrc/edst; +fsrc on y==0) ----------------
__global__ void __launch_bounds__(256, 2)
node_mma_kernel(const float* __restrict__ nodef,
                const float* __restrict__ b_src, const float* __restrict__ b_dst)
{
    extern __shared__ char smem[];
    const uint32_t sb = smem_to_u32(smem);
    const int tid = threadIdx.x;
    const int lane = tid & 31;
    const int wid = tid >> 5;
    const int warp_m = wid & 1;
    const int warp_n = wid >> 1;
    const int tile = blockIdx.x;          // 64 node rows
    const int mtx = blockIdx.y;           // 0 -> w_src/esrc, 1 -> w_dst/edst

    const int arow = tid >> 2;
    const int au = tid & 3;
    int row_g = tile * 64 + arow;
    if (row_g >= NN) row_g = NN - 1;      // clamp (results discarded)
    const float* gA = nodef + (size_t)row_g * DD + au * 8;
    const uint4* gB = g_Bsw + (size_t)(mtx + 1) * 8192;

    MmaCtx ctx;
    run_mainloop(ctx, sb, gA, gB, tid, lane, warp_m, warp_n, arow, au);

    const float* bias = mtx ? b_dst : b_src;
    float* outp = mtx ? g_edst : g_esrc;
    const int q = lane & 3;
    const int odd = q & 1;
    const int ccl = warp_n * 64 + ((q >> 1) << 2) + (odd << 3);

    float4 bbv[4];
    #pragma unroll
    for (int ntp = 0; ntp < 4; ntp++)
        bbv[ntp] = *(const float4*)(bias + ccl + ntp * 16);

    #pragma unroll
    for (int mt = 0; mt < 2; mt++) {
        #pragma unroll
        for (int rh = 0; rh < 2; rh++) {
            int r = warp_m * 32 + mt * 16 + rh * 8 + (lane >> 2);
            int rg = tile * 64 + r;
            bool valid = rg < NN;
            float nrm = 0.f;
            if (mtx == 0 && valid) nrm = rsqrtf(fmaxf(g_outdeg[rg], 1.f));
            #pragma unroll
            for (int ntp = 0; ntp < 4; ntp++) {
                float4 dv = quad_f4(ctx, mt, rh, ntp, odd);   // warp-uniform shfl
                if (!valid) continue;
                int cc = ccl + ntp * 16;
                float4 bb = bbv[ntp];
                float4 o;
                o.x = dv.x + bb.x; o.y = dv.y + bb.y;
                o.z = dv.z + bb.z; o.w = dv.w + bb.w;
                *(float4*)(outp + (size_t)rg * DD + cc) = o;
                if (mtx == 0) {
                    float4 nf = *(const float4*)(nodef + (size_t)rg * DD + cc);
                    float4 fo;
                    fo.x = nf.x * nrm; fo.y = nf.y * nrm;
                    fo.z = nf.z * nrm; fo.w = nf.w * nrm;
                    *(float4*)(g_fsrc + (size_t)rg * DD + cc) = fo;
                }
            }
        }
    }
    CP_WAIT_ALL();
}

// ---------------- launch 3 (profiled): edge GEMM + fused epilogue ----------------
__global__ void __launch_bounds__(256, 2)
edge_mma_kernel(const float* __restrict__ edgef, const int* __restrict__ src,
                const int* __restrict__ dst, const float* __restrict__ b_edge,
                float* __restrict__ m_out)
{
    extern __shared__ char smem[];
    const uint32_t sb = smem_to_u32(smem);
    const int tid = threadIdx.x;
    const int lane = tid & 31;
    const int wid = tid >> 5;
    const int warp_m = wid & 1;
    const int warp_n = wid >> 1;
    const int tile = blockIdx.x;

    const int arow = tid >> 2;
    const int au = tid & 3;
    const float* gA = edgef + (size_t)(tile * 64 + arow) * DD + au * 8;

    if (tid < 64) {
        ((int*)(smem + S_IDX))[tid] = src[tile * 64 + tid];
        ((int*)(smem + S_IDX + 256))[tid] = dst[tile * 64 + tid];
    }

    MmaCtx ctx;
    run_mainloop(ctx, sb, gA, g_Bsw, tid, lane, warp_m, warp_n, arow, au);

    const int q = lane & 3;
    const int odd = q & 1;
    const int ccl = warp_n * 64 + ((q >> 1) << 2) + (odd << 3);

    float4 bbv[4];
    #pragma unroll
    for (int ntp = 0; ntp < 4; ntp++)
        bbv[ntp] = *(const float4*)(b_edge + ccl + ntp * 16);

    #pragma unroll
    for (int mt = 0; mt < 2; mt++) {
        #pragma unroll
        for (int rh = 0; rh < 2; rh++) {
            int r = warp_m * 32 + mt * 16 + rh * 8 + (lane >> 2);
            int e = tile * 64 + r;
            int sN = ((const int*)(smem + S_IDX))[r];
            int dN = ((const int*)(smem + S_IDX + 256))[r];
            const float* pe1 = g_esrc + (size_t)sN * DD;
            const float* pe2 = g_edst + (size_t)dN * DD;
            const float* pf  = g_fsrc + (size_t)sN * DD;
            float* pm = m_out + (size_t)e * DD;
            float* pa = g_agg + (size_t)dN * DD;
            #pragma unroll
            for (int ntp = 0; ntp < 4; ntp++) {
                float4 dv = quad_f4(ctx, mt, rh, ntp, odd);
                int cc = ccl + ntp * 16;
                float4 bb = bbv[ntp];
                float4 e1 = *(const float4*)(pe1 + cc);
                float4 e2 = *(const float4*)(pe2 + cc);
                float4 f  = *(const float4*)(pf + cc);
                float4 mv;
                mv.x = dv.x + bb.x + e1.x + e2.x;
                mv.y = dv.y + bb.y + e1.y + e2.y;
                mv.z = dv.z + bb.z + e1.z + e2.z;
                mv.w = dv.w + bb.w + e1.w + e2.w;
                // streaming store: m is write-once, keep it out of L2's hot set
                asm volatile("st.global.cs.v4.f32 [%0], {%1,%2,%3,%4};"
                             :: "l"(pm + cc), "f"(mv.x), "f"(mv.y), "f"(mv.z), "f"(mv.w)
                             : "memory");
                float s0 = f.x / (1.f + __expf(-mv.x));
                float s1 = f.y / (1.f + __expf(-mv.y));
                float s2 = f.z / (1.f + __expf(-mv.z));
                float s3 = f.w / (1.f + __expf(-mv.w));
                asm volatile("red.global.add.v4.f32 [%0], {%1,%2,%3,%4};"
                             :: "l"(pa + cc), "f"(s0), "f"(s1), "f"(s2), "f"(s3) : "memory");
            }
        }
    }
    CP_WAIT_ALL();
}

// ---------------- launch 4: final projection via HMMA ----------------
__global__ void __launch_bounds__(256, 2)
final_mma_kernel(const float* __restrict__ nodef, const float* __restrict__ bias,
                 float* __restrict__ rst)
{
    extern __shared__ char smem[];
    const uint32_t sb = smem_to_u32(smem);
    const int tid = threadIdx.x;
    const int lane = tid & 31;
    const int wid = tid >> 5;
    const int warp_m = wid & 1;
    const int warp_n = wid >> 1;
    const int tile = blockIdx.x;          // 64 node rows

    const int arow = tid >> 2;
    const int au = tid & 3;
    int row_g = tile * 64 + arow;
    if (row_g >= NN) row_g = NN - 1;      // clamp (results discarded)
    const float* gA = (const float*)g_agg + (size_t)row_g * DD + au * 8;
    const uint4* gB = g_Bsw + (size_t)3 * 8192;

    MmaCtx ctx;
    run_mainloop(ctx, sb, gA, gB, tid, lane, warp_m, warp_n, arow, au);

    const int q = lane & 3;
    const int odd = q & 1;
    const int ccl = warp_n * 64 + ((q >> 1) << 2) + (odd << 3);

    float4 bbv[4];
    #pragma unroll
    for (int ntp = 0; ntp < 4; ntp++)
        bbv[ntp] = *(const float4*)(bias + ccl + ntp * 16);

    #pragma unroll
    for (int mt = 0; mt < 2; mt++) {
        #pragma unroll
        for (int rh = 0; rh < 2; rh++) {
            int r = warp_m * 32 + mt * 16 + rh * 8 + (lane >> 2);
            int rg = tile * 64 + r;
            bool valid = rg < NN;
            float nrm = 0.f;
            if (valid) nrm = rsqrtf(fmaxf(g_indeg[rg], 1.f));
            #pragma unroll
            for (int ntp = 0; ntp < 4; ntp++) {
                float4 dv = quad_f4(ctx, mt, rh, ntp, odd);   // warp-uniform shfl
                if (!valid) continue;
                int cc = ccl + ntp * 16;
                float4 bb = bbv[ntp];
                float4 nf = *(const float4*)(nodef + (size_t)rg * DD + cc);
                float4 o;
                o.x = nf.x + dv.x * nrm + bb.x;
                o.y = nf.y + dv.y * nrm + bb.y;
                o.z = nf.z + dv.z * nrm + bb.z;
                o.w = nf.w + dv.w * nrm + bb.w;
                *(float4*)(rst + (size_t)rg * DD + cc) = o;
            }
        }
    }
    CP_WAIT_ALL();
}

extern "C" void kernel_launch(void* const* d_in, const int* in_sizes, int n_in,
                              void* d_out, int out_size) {
    const float* nodef  = (const float*)d_in[0];
    const float* edgef  = (const float*)d_in[1];
    const int*   src    = (const int*)d_in[2];
    const int*   dst    = (const int*)d_in[3];
    const float* weight = (const float*)d_in[4];
    const float* bias   = (const float*)d_in[5];
    const float* w_src  = (const float*)d_in[6];
    const float* b_src  = (const float*)d_in[7];
    const float* w_dst  = (const float*)d_in[8];
    const float* b_dst  = (const float*)d_in[9];
    const float* w_edge = (const float*)d_in[10];
    const float* b_edge = (const float*)d_in[11];

    float* rst   = (float*)d_out;             // [N, D]
    float* m_out = rst + (size_t)NN * DD;     // [E, D]

    static bool attr_set = false;
    if (!attr_set) {
        cudaFuncSetAttribute(edge_mma_kernel, cudaFuncAttributeMaxDynamicSharedMemorySize, S_TOTAL);
        cudaFuncSetAttribute(node_mma_kernel, cudaFuncAttributeMaxDynamicSharedMemorySize, S_TOTAL);
        cudaFuncSetAttribute(final_mma_kernel, cudaFuncAttributeMaxDynamicSharedMemorySize, S_TOTAL);
        attr_set = true;
    }

    // launch 0: weight prep (4 matrices, fp16) + zero
    fuse0_kernel<<<(NN * DD + 255) / 256, 256>>>(w_edge, w_src, w_dst, weight);
    // launch 1: degrees
    degree_kernel<<<(EE + 255) / 256, 256>>>(src, dst);
    // launch 2: node GEMMs (esrc + fsrc | edst)
    {
        dim3 g((NN + 63) / 64, 2);
        node_mma_kernel<<<g, 256, S_TOTAL>>>(nodef, b_src, b_dst);
    }
    // launch 3 (profiled): edge GEMM + fused epilogue
    edge_mma_kernel<<<EE / 64, 256, S_TOTAL>>>(edgef, src, dst, b_edge, m_out);
    // launch 4: final projection + norm + bias + residual
    final_mma_kernel<<<(NN + 63) / 64, 256, S_TOTAL>>>(nodef, bias, rst);
}

// round 17
// speedup vs baseline: 1.1260x; 1.1260x over previous
#include <cuda_runtime.h>
#include <cuda_fp16.h>
#include <cstdint>

#define NN 10000
#define EE 320000
#define DD 256

// ---------------- scratch (static device globals; no allocation) ----------------
__device__ float g_esrc[NN * DD];
__device__ float g_edst[NN * DD];
__device__ float g_fsrc[NN * DD];
__device__ float g_agg[NN * DD];
__device__ float g_outdeg[NN];
__device__ float g_indeg[NN];
// weights^T as single fp16, pre-swizzled per K32 chunk, paired-row layout.
// matrix m: 0=w_edge, 1=w_src, 2=w_dst, 3=weight ; base = m*8192 (uint4 units)
// within: c*1024 + (n>>1)*8 + (n&1)*4 + (u ^ ((n>>1)&3))
__device__ uint4 g_Bsw[4 * 8192];

// ---------------- helpers ----------------
__device__ __forceinline__ uint32_t smem_to_u32(const void* p) {
    uint32_t a;
    asm("{ .reg .u64 t; cvta.to.shared.u64 t, %1; cvt.u32.u64 %0, t; }" : "=r"(a) : "l"(p));
    return a;
}
__device__ __forceinline__ void ldm_x4(uint32_t& r0, uint32_t& r1, uint32_t& r2, uint32_t& r3,
                                       uint32_t addr) {
    asm volatile("ldmatrix.sync.aligned.m8n8.x4.shared.b16 {%0,%1,%2,%3}, [%4];"
                 : "=r"(r0), "=r"(r1), "=r"(r2), "=r"(r3) : "r"(addr));
}
__device__ __forceinline__ void mma16816(float* c, const uint32_t* a, const uint32_t* b) {
    asm volatile(
        "mma.sync.aligned.m16n8k16.row.col.f32.f16.f16.f32 "
        "{%0,%1,%2,%3}, {%4,%5,%6,%7}, {%8,%9}, {%0,%1,%2,%3};"
        : "+f"(c[0]), "+f"(c[1]), "+f"(c[2]), "+f"(c[3])
        : "r"(a[0]), "r"(a[1]), "r"(a[2]), "r"(a[3]), "r"(b[0]), "r"(b[1]));
}
#define CP_ASYNC16(saddr, gptr) \
    asm volatile("cp.async.cg.shared.global [%0], [%1], 16;" :: "r"(saddr), "l"(gptr) : "memory")
#define CP_COMMIT() asm volatile("cp.async.commit_group;" ::: "memory")
#define CP_WAIT_ALL() asm volatile("cp.async.wait_group 0;" ::: "memory")

__device__ __forceinline__ uint32_t pack_f16(float a, float b) {
    __half ha = __float2half(a), hb = __float2half(b);
    return ((uint32_t)__half_as_ushort(hb) << 16) | (uint32_t)__half_as_ushort(ha);
}

// ---------------- launch 0: weight prep (4 matrices, single fp16) + zero ----------------
__global__ void fuse0_kernel(const float* __restrict__ w_edge,
                             const float* __restrict__ w_src,
                             const float* __restrict__ w_dst,
                             const float* __restrict__ weight) {
    int t = blockIdx.x * blockDim.x + threadIdx.x;
    if (t < NN * DD) g_agg[t] = 0.f;
    if (t < NN) { g_outdeg[t] = 0.f; g_indeg[t] = 0.f; }
    if (t < 4 * 8192) {
        int m = t >> 13;                // matrix id
        int w = t & 8191;
        int n = w & 255;
        int g = w >> 8;                 // 0..31
        int c = g >> 2, u = g & 3;      // K32 chunk, k8-unit
        const float* W = (m == 0) ? w_edge : (m == 1) ? w_src : (m == 2) ? w_dst : weight;
        uint32_t p[4];
        #pragma unroll
        for (int j = 0; j < 4; j++) {
            int k = c * 32 + u * 8 + 2 * j;
            p[j] = pack_f16(W[(size_t)k * DD + n], W[(size_t)(k + 1) * DD + n]);
        }
        int di = m * 8192 + c * 1024 + (n >> 1) * 8 + (n & 1) * 4 + (u ^ ((n >> 1) & 3));
        g_Bsw[di] = make_uint4(p[0], p[1], p[2], p[3]);
    }
}

// ---------------- launch 1: degrees ----------------
__global__ void degree_kernel(const int* __restrict__ src, const int* __restrict__ dst) {
    int e = blockIdx.x * blockDim.x + threadIdx.x;
    if (e < EE) {
        atomicAdd(&g_outdeg[src[e]], 1.f);
        atomicAdd(&g_indeg[dst[e]], 1.f);
    }
}

// ---------------- SMEM layout for MMA kernels (per CTA) ----------------
// B ring: 2 slots x 16KB = 32KB ; A: 2 bufs x 4KB = 8KB (single fp16)
static constexpr int S_B   = 0;
static constexpr int S_A   = 32768;
static constexpr int S_IDX = 40960;      // 64 src + 64 dst ints = 512B
static constexpr int S_TOTAL = 41472;

// paired-row swizzled offset for a (row, k8-unit) 16B tile
__device__ __forceinline__ uint32_t prow_off(uint32_t r, uint32_t u) {
    return (r >> 1) * 128u + (r & 1) * 64u + ((u ^ ((r >> 1) & 3u)) << 4);
}

// =====================================================================
// Shared mainloop: acc[2][8][4] = A(64 x 256, single fp16) @ B16^T
// =====================================================================
struct MmaCtx {
    float acc[2][8][4];
};

__device__ __forceinline__ void run_mainloop(
    MmaCtx& ctx, uint32_t sb, const float* gA, const uint4* gB,
    int tid, int lane, int warp_m, int warp_n, int arow, int au)
{
    #pragma unroll
    for (int mt = 0; mt < 2; mt++)
        #pragma unroll
        for (int nt = 0; nt < 8; nt++)
            #pragma unroll
            for (int i = 0; i < 4; i++) ctx.acc[mt][nt][i] = 0.f;

    // prologue: B chunk 0 into slot 0 (16KB = 1024 units)
    #pragma unroll
    for (int i = 0; i < 4; i++) {
        int idx = tid + i * 256;
        CP_ASYNC16(sb + S_B + idx * 16, gB + idx);
    }
    CP_COMMIT();

    // A(0): load + convert into Abuf0
    float4 rx0 = *(const float4*)(gA);
    float4 rx1 = *(const float4*)(gA + 4);
    {
        uint32_t h0 = pack_f16(rx0.x, rx0.y);
        uint32_t h1 = pack_f16(rx0.z, rx0.w);
        uint32_t h2 = pack_f16(rx1.x, rx1.y);
        uint32_t h3 = pack_f16(rx1.z, rx1.w);
        uint32_t off = prow_off(arow, au);
        asm volatile("st.shared.v4.b32 [%0], {%1,%2,%3,%4};"
                     :: "r"(sb + S_A + off), "r"(h0), "r"(h1), "r"(h2), "r"(h3) : "memory");
    }
    rx0 = *(const float4*)(gA + 32);
    rx1 = *(const float4*)(gA + 36);

    CP_WAIT_ALL();
    __syncthreads();

    const uint32_t a_row = (uint32_t)(lane & 15);
    const uint32_t a_kh  = (uint32_t)(lane >> 4);
    const uint32_t b_nl  = (uint32_t)((lane & 7) + ((lane >> 4) << 3));
    const uint32_t b_kh  = (uint32_t)((lane >> 3) & 1);

    #pragma unroll 1
    for (int s = 0; s < 8; s++) {
        const uint32_t bbase = sb + S_B + (uint32_t)(s & 1) * 16384u;
        const uint32_t abase = sb + S_A + (uint32_t)(s & 1) * 4096u;

        if (s < 7) {
            const uint4* bsrc = gB + (s + 1) * 1024;
            const uint32_t slot = sb + S_B + (uint32_t)((s + 1) & 1) * 16384u;
            #pragma unroll
            for (int i = 0; i < 4; i++) {
                int idx = tid + i * 256;
                CP_ASYNC16(slot + idx * 16, bsrc + idx);
            }
            CP_COMMIT();
        }

        #pragma unroll
        for (int ks = 0; ks < 2; ks++) {
            uint32_t ah[2][4];
            #pragma unroll
            for (int mt = 0; mt < 2; mt++) {
                uint32_t r = (uint32_t)(warp_m * 32 + mt * 16) + a_row;
                uint32_t u = (uint32_t)(ks * 2) + a_kh;
                uint32_t off = prow_off(r, u);
                ldm_x4(ah[mt][0], ah[mt][1], ah[mt][2], ah[mt][3], abase + off);
            }
            #pragma unroll
            for (int j = 0; j < 4; j++) {
                uint32_t n = (uint32_t)(warp_n * 64 + j * 16) + b_nl;
                uint32_t u = (uint32_t)(ks * 2) + b_kh;
                uint32_t boff = prow_off(n, u);
                uint32_t bf[4];
                ldm_x4(bf[0], bf[1], bf[2], bf[3], bbase + boff);
                #pragma unroll
                for (int mt = 0; mt < 2; mt++) {
                    mma16816(ctx.acc[mt][2 * j + 0], ah[mt], bf + 0);
                    mma16816(ctx.acc[mt][2 * j + 1], ah[mt], bf + 2);
                }
            }
        }

        if (s < 7) {
            uint32_t h0 = pack_f16(rx0.x, rx0.y);
            uint32_t h1 = pack_f16(rx0.z, rx0.w);
            uint32_t h2 = pack_f16(rx1.x, rx1.y);
            uint32_t h3 = pack_f16(rx1.z, rx1.w);
            uint32_t dstb = sb + S_A + (uint32_t)((s + 1) & 1) * 4096u + prow_off(arow, au);
            asm volatile("st.shared.v4.b32 [%0], {%1,%2,%3,%4};"
                         :: "r"(dstb), "r"(h0), "r"(h1), "r"(h2), "r"(h3) : "memory");
            if (s < 6) {
                rx0 = *(const float4*)(gA + (s + 2) * 32);
                rx1 = *(const float4*)(gA + (s + 2) * 32 + 4);
            }
            CP_WAIT_ALL();
            __syncthreads();
        }
    }
}

// assemble this lane's float4 for nt-pair ntp via quad shfl (warp-uniform)
__device__ __forceinline__ float4 quad_f4(const MmaCtx& ctx, int mt, int rh, int ntp, int odd) {
    float v0x = ctx.acc[mt][2 * ntp + 0][rh * 2 + 0];
    float v0y = ctx.acc[mt][2 * ntp + 0][rh * 2 + 1];
    float v1x = ctx.acc[mt][2 * ntp + 1][rh * 2 + 0];
    float v1y = ctx.acc[mt][2 * ntp + 1][rh * 2 + 1];
    float t0 = __shfl_xor_sync(0xffffffffu, v0x, 1);
    float t1 = __shfl_xor_sync(0xffffffffu, v0y, 1);
    float t2 = __shfl_xor_sync(0xffffffffu, v1x, 1);
    float t3 = __shfl_xor_sync(0xffffffffu, v1y, 1);
    float4 dv;
    dv.x = odd ? t2  : v0x;
    dv.y = odd ? t3  : v0y;
    dv.z = odd ? v1x : t0;
    dv.w = odd ? v1y : t1;
    return dv;
}

// ---------------- launch 2: node GEMMs (esrc/edst; +fsrc on y==0) ----------------
__global__ void __launch_bounds__(256, 2)
node_mma_kernel(const float* __restrict__ nodef,
                const float* __restrict__ b_src, const float* __restrict__ b_dst)
{
    extern __shared__ char smem[];
    const uint32_t sb = smem_to_u32(smem);
    const int tid = threadIdx.x;
    const int lane = tid & 31;
    const int wid = tid >> 5;
    const int warp_m = wid & 1;
    const int warp_n = wid >> 1;
    const int tile = blockIdx.x;          // 64 node rows
    const int mtx = blockIdx.y;           // 0 -> w_src/esrc, 1 -> w_dst/edst

    const int arow = tid >> 2;
    const int au = tid & 3;
    int row_g = tile * 64 + arow;
    if (row_g >= NN) row_g = NN - 1;      // clamp (results discarded)
    const float* gA = nodef + (size_t)row_g * DD + au * 8;
    const uint4* gB = g_Bsw + (size_t)(mtx + 1) * 8192;

    MmaCtx ctx;
    run_mainloop(ctx, sb, gA, gB, tid, lane, warp_m, warp_n, arow, au);

    const float* bias = mtx ? b_dst : b_src;
    float* outp = mtx ? g_edst : g_esrc;
    const int q = lane & 3;
    const int odd = q & 1;
    const int ccl = warp_n * 64 + ((q >> 1) << 2) + (odd << 3);

    float4 bbv[4];
    #pragma unroll
    for (int ntp = 0; ntp < 4; ntp++)
        bbv[ntp] = *(const float4*)(bias + ccl + ntp * 16);

    #pragma unroll
    for (int mt = 0; mt < 2; mt++) {
        #pragma unroll
        for (int rh = 0; rh < 2; rh++) {
            int r = warp_m * 32 + mt * 16 + rh * 8 + (lane >> 2);
            int rg = tile * 64 + r;
            bool valid = rg < NN;
            float nrm = 0.f;
            if (mtx == 0 && valid) nrm = rsqrtf(fmaxf(g_outdeg[rg], 1.f));
            #pragma unroll
            for (int ntp = 0; ntp < 4; ntp++) {
                float4 dv = quad_f4(ctx, mt, rh, ntp, odd);   // warp-uniform shfl
                if (!valid) continue;
                int cc = ccl + ntp * 16;
                float4 bb = bbv[ntp];
                float4 o;
                o.x = dv.x + bb.x; o.y = dv.y + bb.y;
                o.z = dv.z + bb.z; o.w = dv.w + bb.w;
                *(float4*)(outp + (size_t)rg * DD + cc) = o;
                if (mtx == 0) {
                    float4 nf = *(const float4*)(nodef + (size_t)rg * DD + cc);
                    float4 fo;
                    fo.x = nf.x * nrm; fo.y = nf.y * nrm;
                    fo.z = nf.z * nrm; fo.w = nf.w * nrm;
                    *(float4*)(g_fsrc + (size_t)rg * DD + cc) = fo;
                }
            }
        }
    }
    CP_WAIT_ALL();
}

// ---------------- launch 3 (profiled): edge GEMM + fused epilogue ----------------
__global__ void __launch_bounds__(256, 2)
edge_mma_kernel(const float* __restrict__ edgef, const int* __restrict__ src,
                const int* __restrict__ dst, const float* __restrict__ b_edge,
                float* __restrict__ m_out)
{
    extern __shared__ char smem[];
    const uint32_t sb = smem_to_u32(smem);
    const int tid = threadIdx.x;
    const int lane = tid & 31;
    const int wid = tid >> 5;
    const int warp_m = wid & 1;
    const int warp_n = wid >> 1;
    const int tile = blockIdx.x;

    const int arow = tid >> 2;
    const int au = tid & 3;
    const float* gA = edgef + (size_t)(tile * 64 + arow) * DD + au * 8;

    if (tid < 64) {
        ((int*)(smem + S_IDX))[tid] = src[tile * 64 + tid];
        ((int*)(smem + S_IDX + 256))[tid] = dst[tile * 64 + tid];
    }

    MmaCtx ctx;
    run_mainloop(ctx, sb, gA, g_Bsw, tid, lane, warp_m, warp_n, arow, au);

    const int q = lane & 3;
    const int odd = q & 1;
    const int ccl = warp_n * 64 + ((q >> 1) << 2) + (odd << 3);

    float4 bbv[4];
    #pragma unroll
    for (int ntp = 0; ntp < 4; ntp++)
        bbv[ntp] = *(const float4*)(b_edge + ccl + ntp * 16);

    #pragma unroll
    for (int mt = 0; mt < 2; mt++) {
        #pragma unroll
        for (int rh = 0; rh < 2; rh++) {
            int r = warp_m * 32 + mt * 16 + rh * 8 + (lane >> 2);
            int e = tile * 64 + r;
            int sN = ((const int*)(smem + S_IDX))[r];
            int dN = ((const int*)(smem + S_IDX + 256))[r];
            const float* pe1 = g_esrc + (size_t)sN * DD;
            const float* pe2 = g_edst + (size_t)dN * DD;
            const float* pf  = g_fsrc + (size_t)sN * DD;
            float* pm = m_out + (size_t)e * DD;
            float* pa = g_agg + (size_t)dN * DD;
            #pragma unroll
            for (int ntp = 0; ntp < 4; ntp++) {
                float4 dv = quad_f4(ctx, mt, rh, ntp, odd);
                int cc = ccl + ntp * 16;
                float4 bb = bbv[ntp];
                float4 e1 = *(const float4*)(pe1 + cc);
                float4 e2 = *(const float4*)(pe2 + cc);
                float4 f  = *(const float4*)(pf + cc);
                float4 mv;
                mv.x = dv.x + bb.x + e1.x + e2.x;
                mv.y = dv.y + bb.y + e1.y + e2.y;
                mv.z = dv.z + bb.z + e1.z + e2.z;
                mv.w = dv.w + bb.w + e1.w + e2.w;
                // streaming store: m is write-once, keep it out of L2's hot set
                asm volatile("st.global.cs.v4.f32 [%0], {%1,%2,%3,%4};"
                             :: "l"(pm + cc), "f"(mv.x), "f"(mv.y), "f"(mv.z), "f"(mv.w)
                             : "memory");
                float s0 = f.x / (1.f + __expf(-mv.x));
                float s1 = f.y / (1.f + __expf(-mv.y));
                float s2 = f.z / (1.f + __expf(-mv.z));
                float s3 = f.w / (1.f + __expf(-mv.w));
                asm volatile("red.global.add.v4.f32 [%0], {%1,%2,%3,%4};"
                             :: "l"(pa + cc), "f"(s0), "f"(s1), "f"(s2), "f"(s3) : "memory");
            }
        }
    }
    CP_WAIT_ALL();
}

// ---------------- launch 4: final projection via HMMA ----------------
__global__ void __launch_bounds__(256, 2)
final_mma_kernel(const float* __restrict__ nodef, const float* __restrict__ bias,
                 float* __restrict__ rst)
{
    extern __shared__ char smem[];
    const uint32_t sb = smem_to_u32(smem);
    const int tid = threadIdx.x;
    const int lane = tid & 31;
    const int wid = tid >> 5;
    const int warp_m = wid & 1;
    const int warp_n = wid >> 1;
    const int tile = blockIdx.x;          // 64 node rows

    const int arow = tid >> 2;
    const int au = tid & 3;
    int row_g = tile * 64 + arow;
    if (row_g >= NN) row_g = NN - 1;      // clamp (results discarded)
    const float* gA = (const float*)g_agg + (size_t)row_g * DD + au * 8;
    const uint4* gB = g_Bsw + (size_t)3 * 8192;

    MmaCtx ctx;
    run_mainloop(ctx, sb, gA, gB, tid, lane, warp_m, warp_n, arow, au);

    const int q = lane & 3;
    const int odd = q & 1;
    const int ccl = warp_n * 64 + ((q >> 1) << 2) + (odd << 3);

    float4 bbv[4];
    #pragma unroll
    for (int ntp = 0; ntp < 4; ntp++)
        bbv[ntp] = *(const float4*)(bias + ccl + ntp * 16);

    #pragma unroll
    for (int mt = 0; mt < 2; mt++) {
        #pragma unroll
        for (int rh = 0; rh < 2; rh++) {
            int r = warp_m * 32 + mt * 16 + rh * 8 + (lane >> 2);
            int rg = tile * 64 + r;
            bool valid = rg < NN;
            float nrm = 0.f;
            if (valid) nrm = rsqrtf(fmaxf(g_indeg[rg], 1.f));
            #pragma unroll
            for (int ntp = 0; ntp < 4; ntp++) {
                float4 dv = quad_f4(ctx, mt, rh, ntp, odd);   // warp-uniform shfl
                if (!valid) continue;
                int cc = ccl + ntp * 16;
                float4 bb = bbv[ntp];
                float4 nf = *(const float4*)(nodef + (size_t)rg * DD + cc);
                float4 o;
                o.x = nf.x + dv.x * nrm + bb.x;
                o.y = nf.y + dv.y * nrm + bb.y;
                o.z = nf.z + dv.z * nrm + bb.z;
                o.w = nf.w + dv.w * nrm + bb.w;
                *(float4*)(rst + (size_t)rg * DD + cc) = o;
            }
        }
    }
    CP_WAIT_ALL();
}

extern "C" void kernel_launch(void* const* d_in, const int* in_sizes, int n_in,
                              void* d_out, int out_size) {
    const float* nodef  = (const float*)d_in[0];
    const float* edgef  = (const float*)d_in[1];
    const int*   src    = (const int*)d_in[2];
    const int*   dst    = (const int*)d_in[3];
    const float* weight = (const float*)d_in[4];
    const float* bias   = (const float*)d_in[5];
    const float* w_src  = (const float*)d_in[6];
    const float* b_src  = (const float*)d_in[7];
    const float* w_dst  = (const float*)d_in[8];
    const float* b_dst  = (const float*)d_in[9];
    const float* w_edge = (const float*)d_in[10];
    const float* b_edge = (const float*)d_in[11];

    float* rst   = (float*)d_out;             // [N, D]
    float* m_out = rst + (size_t)NN * DD;     // [E, D]

    static bool attr_set = false;
    if (!attr_set) {
        cudaFuncSetAttribute(edge_mma_kernel, cudaFuncAttributeMaxDynamicSharedMemorySize, S_TOTAL);
        cudaFuncSetAttribute(node_mma_kernel, cudaFuncAttributeMaxDynamicSharedMemorySize, S_TOTAL);
        cudaFuncSetAttribute(final_mma_kernel, cudaFuncAttributeMaxDynamicSharedMemorySize, S_TOTAL);
        attr_set = true;
    }

    // launch 0: weight prep (4 matrices, fp16) + zero
    fuse0_kernel<<<(NN * DD + 255) / 256, 256>>>(w_edge, w_src, w_dst, weight);
    // launch 1: degrees
    degree_kernel<<<(EE + 255) / 256, 256>>>(src, dst);
    // launch 2: node GEMMs (esrc + fsrc | edst)
    {
        dim3 g((NN + 63) / 64, 2);
        node_mma_kernel<<<g, 256, S_TOTAL>>>(nodef, b_src, b_dst);
    }
    // launch 3 (profiled): edge GEMM + fused epilogue
    edge_mma_kernel<<<EE / 64, 256, S_TOTAL>>>(edgef, src, dst, b_edge, m_out);
    // launch 4: final projection + norm + bias + residual
    final_mma_kernel<<<(NN + 63) / 64, 256, S_TOTAL>>>(nodef, bias, rst);
}